// round 3
// baseline (speedup 1.0000x reference)
#include <cuda_runtime.h>
#include <math.h>

#define BATCHN 2048
#define SEQN   512
#define INPN   128
#define HIDN   256
#define OUTN   64
#define ROWS   16      // batch rows per CTA
#define NTHR   512     // 16 warps: warp w owns row w in phase B
#define HPAD   18      // padded row stride for [k][r] smem arrays (even for LDS.64 align)
#define FEPS   1e-8f

__device__ __forceinline__ float wsum(float v) {
    v += __shfl_xor_sync(0xffffffffu, v, 16);
    v += __shfl_xor_sync(0xffffffffu, v, 8);
    v += __shfl_xor_sync(0xffffffffu, v, 4);
    v += __shfl_xor_sync(0xffffffffu, v, 2);
    v += __shfl_xor_sync(0xffffffffu, v, 1);
    return v;
}

__global__ void __launch_bounds__(NTHR, 1) nlnn_kernel(
    const float* __restrict__ x,        // [B, S, 128]
    const float* __restrict__ h_init,   // [B, 256]
    const float* __restrict__ Win,      // [128, 256]
    const float* __restrict__ Wrec,     // [256, 256]
    const float* __restrict__ Wout,     // [256, 64]
    const float* __restrict__ lam_i,    // [256]
    const float* __restrict__ lam_r,    // [256]
    const float* __restrict__ s_z_p,    // [1]
    const float* __restrict__ alpha_raw,// [256]
    float* __restrict__ outp,           // [B, S, 64]
    float* __restrict__ hfin)           // [B, 256] or null
{
    __shared__ float hs[HIDN * HPAD];   // h[k][r]
    __shared__ float xs[INPN * HPAD];   // x[k][r]
    __shared__ float vs[ROWS * HIDN];   // v[r][j]

    const int tid  = threadIdx.x;
    const int b0   = blockIdx.x * ROWS;

    // GEMM-phase mapping: 64 j-groups (4 cols) x 8 row-groups (2 rows)
    const int jg = tid & 63;
    const int rg = tid >> 6;
    const int j4 = jg * 4;
    const int r2 = rg * 2;

    // Row-warp mapping: warp w <-> batch row w of this CTA
    const int w    = tid >> 5;
    const int lane = tid & 31;

    // Persistent per-row state: lane holds h[row][lane + 32*i]
    float hh[8];
    float al[8];
#pragma unroll
    for (int i = 0; i < 8; ++i) {
        int j = lane + 32 * i;
        hh[i] = h_init[(size_t)(b0 + w) * HIDN + j];
        float a = alpha_raw[j];
        al[i] = 1.0f / (1.0f + expf(-a));
    }
#pragma unroll
    for (int i = 0; i < 8; ++i)
        hs[(lane + 32 * i) * HPAD + w] = hh[i];

    const float4 liv = *(const float4*)(lam_i + j4);
    const float4 lrv = *(const float4*)(lam_r + j4);
    const float  s_z = s_z_p[0];

    const float* __restrict__ wi = Win  + j4;
    const float* __restrict__ wr = Wrec + j4;
    const float* __restrict__ wo = Wout + 2 * lane;

    __syncthreads();

    for (int t = 0; t < SEQN; ++t) {
        // ---- load x_t (warp w loads row w, coalesced) ----
        {
            int k4 = lane * 4;
            float4 xv = *(const float4*)(x + ((size_t)(b0 + w) * SEQN + t) * INPN + k4);
            xs[(k4 + 0) * HPAD + w] = xv.x;
            xs[(k4 + 1) * HPAD + w] = xv.y;
            xs[(k4 + 2) * HPAD + w] = xv.z;
            xs[(k4 + 3) * HPAD + w] = xv.w;
        }
        __syncthreads();

        // ---- input GEMM: acc = x_t @ Win (2 rows x 4 cols per thread) ----
        float a00 = 0.f, a01 = 0.f, a02 = 0.f, a03 = 0.f;
        float a10 = 0.f, a11 = 0.f, a12 = 0.f, a13 = 0.f;
#pragma unroll 8
        for (int k = 0; k < INPN; ++k) {
            float4 wv = *(const float4*)(wi + (size_t)k * HIDN);
            float2 hv = *(const float2*)(&xs[k * HPAD + r2]);
            a00 = fmaf(hv.x, wv.x, a00); a01 = fmaf(hv.x, wv.y, a01);
            a02 = fmaf(hv.x, wv.z, a02); a03 = fmaf(hv.x, wv.w, a03);
            a10 = fmaf(hv.y, wv.x, a10); a11 = fmaf(hv.y, wv.y, a11);
            a12 = fmaf(hv.y, wv.z, a12); a13 = fmaf(hv.y, wv.w, a13);
        }
        float v00 = liv.x * a00, v01 = liv.y * a01, v02 = liv.z * a02, v03 = liv.w * a03;
        float v10 = liv.x * a10, v11 = liv.y * a11, v12 = liv.z * a12, v13 = liv.w * a13;

        // ---- recurrent GEMM: acc = h_t @ Wrec ----
        a00 = a01 = a02 = a03 = a10 = a11 = a12 = a13 = 0.f;
#pragma unroll 8
        for (int k = 0; k < HIDN; ++k) {
            float4 wv = *(const float4*)(wr + (size_t)k * HIDN);
            float2 hv = *(const float2*)(&hs[k * HPAD + r2]);
            a00 = fmaf(hv.x, wv.x, a00); a01 = fmaf(hv.x, wv.y, a01);
            a02 = fmaf(hv.x, wv.z, a02); a03 = fmaf(hv.x, wv.w, a03);
            a10 = fmaf(hv.y, wv.x, a10); a11 = fmaf(hv.y, wv.y, a11);
            a12 = fmaf(hv.y, wv.z, a12); a13 = fmaf(hv.y, wv.w, a13);
        }
        v00 = fmaf(lrv.x, a00, v00); v01 = fmaf(lrv.y, a01, v01);
        v02 = fmaf(lrv.z, a02, v02); v03 = fmaf(lrv.w, a03, v03);
        v10 = fmaf(lrv.x, a10, v10); v11 = fmaf(lrv.y, a11, v11);
        v12 = fmaf(lrv.z, a12, v12); v13 = fmaf(lrv.w, a13, v13);

        *(float4*)(&vs[(r2 + 0) * HIDN + j4]) = make_float4(v00, v01, v02, v03);
        *(float4*)(&vs[(r2 + 1) * HIDN + j4]) = make_float4(v10, v11, v12, v13);
        __syncthreads();

        // ---- phase B: warp w processes row w ----
        float vv[8];
        float ssq = 0.f;
#pragma unroll
        for (int i = 0; i < 8; ++i) {
            vv[i] = vs[w * HIDN + lane + 32 * i];
            ssq = fmaf(vv[i], vv[i], ssq);
        }
        ssq = wsum(ssq);
        float ninv = 1.0f / (sqrtf(ssq) + FEPS);

        float hsq = 0.f;
#pragma unroll
        for (int i = 0; i < 8; ++i) hsq = fmaf(hh[i], hh[i], hsq);
        hsq = wsum(hsq);
        float hinv = 1.0f / (sqrtf(hsq) + FEPS);

        float dot = 0.f;
        float hn[8], ht[8];
#pragma unroll
        for (int i = 0; i < 8; ++i) {
            hn[i] = vv[i] * ninv;
            ht[i] = hh[i] * hinv;
            dot = fmaf(ht[i], hn[i], dot);
        }
        dot = wsum(dot);
        dot = fminf(fmaxf(dot, -1.0f + FEPS), 1.0f - FEPS);
        float theta = acosf(dot);
        float st    = __sinf(theta);
        float inv_st = 1.0f / (st + FEPS);
        bool  mask   = (st > FEPS);

        float res[8];
        float rsq = 0.f;
#pragma unroll
        for (int i = 0; i < 8; ++i) {
            float ct = __sinf((1.0f - al[i]) * theta) * inv_st;
            float cn = __sinf(al[i] * theta) * inv_st;
            float r  = fmaf(ct, ht[i], cn * hn[i]);
            r = mask ? r : hn[i];
            res[i] = r;
            rsq = fmaf(r, r, rsq);
        }
        rsq = wsum(rsq);
        float rinv = 1.0f / (sqrtf(rsq) + FEPS);
#pragma unroll
        for (int i = 0; i < 8; ++i) {
            hh[i] = res[i] * rinv;
            hs[(lane + 32 * i) * HPAD + w] = hh[i];   // for next step's GEMM
        }

        // ---- output GEMM: out[w][2*lane .. 2*lane+1], h broadcast via shuffle ----
        float o0 = 0.f, o1 = 0.f;
#pragma unroll
        for (int i = 0; i < 8; ++i) {
#pragma unroll
            for (int src = 0; src < 32; ++src) {
                float hk = __shfl_sync(0xffffffffu, hh[i], src);
                int k = src + 32 * i;
                float2 w2 = *(const float2*)(wo + (size_t)k * OUTN);
                o0 = fmaf(hk, w2.x, o0);
                o1 = fmaf(hk, w2.y, o1);
            }
        }
        *(float2*)(outp + ((size_t)(b0 + w) * SEQN + t) * OUTN + 2 * lane)
            = make_float2(s_z * o0, s_z * o1);
        // hs writes above are consumed only after next loop's __syncthreads()
    }

    if (hfin) {
#pragma unroll
        for (int i = 0; i < 8; ++i)
            hfin[(size_t)(b0 + w) * HIDN + lane + 32 * i] = hh[i];
    }
}

extern "C" void kernel_launch(void* const* d_in, const int* in_sizes, int n_in,
                              void* d_out, int out_size) {
    const float* x      = (const float*)d_in[0];
    const float* h_init = (const float*)d_in[1];
    const float* Win    = (const float*)d_in[2];
    const float* Wrec   = (const float*)d_in[3];
    const float* Wout   = (const float*)d_in[4];
    const float* li     = (const float*)d_in[5];
    const float* lr     = (const float*)d_in[6];
    const float* sz     = (const float*)d_in[7];
    const float* ar     = (const float*)d_in[8];

    float* outp = (float*)d_out;
    long long main_elems = (long long)BATCHN * SEQN * OUTN;
    float* hfin = nullptr;
    if ((long long)out_size >= main_elems + (long long)BATCHN * HIDN)
        hfin = outp + main_elems;

    nlnn_kernel<<<BATCHN / ROWS, NTHR>>>(x, h_init, Win, Wrec, Wout,
                                         li, lr, sz, ar, outp, hfin);
}

// round 4
// speedup vs baseline: 2.1170x; 2.1170x over previous
#include <cuda_runtime.h>
#include <math.h>

#define BATCHN 2048
#define SEQN   512
#define INPN   128
#define HIDN   256
#define OUTN   64
#define KTOT   384
#define ROWS   16
#define NTHR   512
#define CSS    20          // cs row stride (floats), mult of 4
#define FEPS   1e-8f

typedef unsigned long long u64t;

__device__ float g_Wcat[KTOT * HIDN];                   // [384][256] lambda-folded
__device__ float g_H[(size_t)BATCHN * SEQN * HIDN];     // h history (1 GB scratch)

__device__ __forceinline__ u64t dup2(float a) {
    u64t r; asm("mov.b64 %0, {%1, %1};" : "=l"(r) : "f"(a)); return r;
}
__device__ __forceinline__ void ffma2(u64t& d, u64t a, u64t b) {
    asm("fma.rn.f32x2 %0, %1, %2, %0;" : "+l"(d) : "l"(a), "l"(b));
}
__device__ __forceinline__ float lo2(u64t v) { return __uint_as_float((unsigned)v); }
__device__ __forceinline__ float hi2(u64t v) { return __uint_as_float((unsigned)(v >> 32)); }

__device__ __forceinline__ float wsum(float v) {
    v += __shfl_xor_sync(0xffffffffu, v, 16);
    v += __shfl_xor_sync(0xffffffffu, v, 8);
    v += __shfl_xor_sync(0xffffffffu, v, 4);
    v += __shfl_xor_sync(0xffffffffu, v, 2);
    v += __shfl_xor_sync(0xffffffffu, v, 1);
    return v;
}

__global__ void prep_kernel(const float* __restrict__ Win, const float* __restrict__ Wrec,
                            const float* __restrict__ li,  const float* __restrict__ lr) {
    int k = blockIdx.x, j = threadIdx.x;
    g_Wcat[k * HIDN + j] = (k < HIDN) ? lr[j] * Wrec[k * HIDN + j]
                                      : li[j] * Win[(k - HIDN) * HIDN + j];
}

__global__ void __launch_bounds__(NTHR, 1) nlnn_main(
    const float* __restrict__ x,         // [B,S,128]
    const float* __restrict__ h_init,    // [B,256]
    const float* __restrict__ alpha_raw, // [256]
    float* __restrict__ hfin)
{
    extern __shared__ float smem[];
    float* cs    = smem;                 // [384][CSS]: k<256 h, k>=256 x
    float* vpart = smem + KTOT * CSS;    // [4][16][256]

    const int tid = threadIdx.x;
    const int b0  = blockIdx.x * ROWS;

    const int jg = tid & 63, rg = (tid >> 6) & 1, kg = tid >> 7;
    const int j4 = jg * 4, r0 = rg * 8;
    const int kbeg = kg * 96;

    const int w = tid >> 5, lane = tid & 31;

    float hh[8], al[8];
#pragma unroll
    for (int i = 0; i < 8; ++i) {
        int j = lane + 32 * i;
        hh[i] = h_init[(size_t)(b0 + w) * HIDN + j];
        al[i] = 1.0f / (1.0f + expf(-alpha_raw[j]));
        cs[j * CSS + w] = hh[i];
    }

    float xr[4];
#pragma unroll
    for (int i = 0; i < 4; ++i)
        xr[i] = x[(size_t)(b0 + w) * SEQN * INPN + lane + 32 * i];

    for (int t = 0; t < SEQN; ++t) {
#pragma unroll
        for (int i = 0; i < 4; ++i)
            cs[(HIDN + lane + 32 * i) * CSS + w] = xr[i];
        __syncthreads();                                   // S1: cs complete

        // ---- phase A: 8 rows x 4 cols, this thread's K-quarter ----
        u64t acc[4][4];
#pragma unroll
        for (int p = 0; p < 4; ++p)
#pragma unroll
            for (int c = 0; c < 4; ++c) acc[p][c] = 0ull;

        const float* wp = g_Wcat + (size_t)kbeg * HIDN + j4;
        const float* cp = cs + kbeg * CSS + r0;
#pragma unroll 8
        for (int kk = 0; kk < 96; ++kk) {
            float4 wv = *(const float4*)(wp + (size_t)kk * HIDN);
            ulonglong2 ha = *(const ulonglong2*)(cp + kk * CSS);     // rows r0..+3
            ulonglong2 hb = *(const ulonglong2*)(cp + kk * CSS + 4); // rows r0+4..+7
            u64t bx = dup2(wv.x), by = dup2(wv.y), bz = dup2(wv.z), bw = dup2(wv.w);
            ffma2(acc[0][0], ha.x, bx); ffma2(acc[0][1], ha.x, by);
            ffma2(acc[0][2], ha.x, bz); ffma2(acc[0][3], ha.x, bw);
            ffma2(acc[1][0], ha.y, bx); ffma2(acc[1][1], ha.y, by);
            ffma2(acc[1][2], ha.y, bz); ffma2(acc[1][3], ha.y, bw);
            ffma2(acc[2][0], hb.x, bx); ffma2(acc[2][1], hb.x, by);
            ffma2(acc[2][2], hb.x, bz); ffma2(acc[2][3], hb.x, bw);
            ffma2(acc[3][0], hb.y, bx); ffma2(acc[3][1], hb.y, by);
            ffma2(acc[3][2], hb.y, bz); ffma2(acc[3][3], hb.y, bw);
        }
        {
            float* vp = vpart + (size_t)(kg * ROWS + r0) * HIDN + j4;
#pragma unroll
            for (int p = 0; p < 4; ++p) {
                *(float4*)(vp + (size_t)(2 * p) * HIDN) =
                    make_float4(lo2(acc[p][0]), lo2(acc[p][1]), lo2(acc[p][2]), lo2(acc[p][3]));
                *(float4*)(vp + (size_t)(2 * p + 1) * HIDN) =
                    make_float4(hi2(acc[p][0]), hi2(acc[p][1]), hi2(acc[p][2]), hi2(acc[p][3]));
            }
        }
        __syncthreads();                                   // S2: partials ready

        // ---- phase B: warp w owns row w ----
        float vv[8], ssq = 0.f;
#pragma unroll
        for (int i = 0; i < 8; ++i) {
            int j = lane + 32 * i;
            float s = vpart[(0 * ROWS + w) * HIDN + j]
                    + vpart[(1 * ROWS + w) * HIDN + j]
                    + vpart[(2 * ROWS + w) * HIDN + j]
                    + vpart[(3 * ROWS + w) * HIDN + j];
            vv[i] = s;
            ssq = fmaf(s, s, ssq);
        }
        ssq = wsum(ssq);
        float ninv = 1.0f / (sqrtf(ssq) + FEPS);

        float hsq = 0.f;
#pragma unroll
        for (int i = 0; i < 8; ++i) hsq = fmaf(hh[i], hh[i], hsq);
        hsq = wsum(hsq);
        float hinv = 1.0f / (sqrtf(hsq) + FEPS);

        float dot = 0.f, hn[8], ht[8];
#pragma unroll
        for (int i = 0; i < 8; ++i) {
            hn[i] = vv[i] * ninv;
            ht[i] = hh[i] * hinv;
            dot = fmaf(ht[i], hn[i], dot);
        }
        dot = wsum(dot);
        dot = fminf(fmaxf(dot, -1.0f + FEPS), 1.0f - FEPS);
        float theta  = acosf(dot);
        float st     = __sinf(theta);
        float inv_st = 1.0f / (st + FEPS);
        bool  mask   = (st > FEPS);

        float res[8], rsq = 0.f;
#pragma unroll
        for (int i = 0; i < 8; ++i) {
            float ct = __sinf((1.0f - al[i]) * theta) * inv_st;
            float cn = __sinf(al[i] * theta) * inv_st;
            float r  = fmaf(ct, ht[i], cn * hn[i]);
            r = mask ? r : hn[i];
            res[i] = r;
            rsq = fmaf(r, r, rsq);
        }
        rsq = wsum(rsq);
        float rinv = 1.0f / (sqrtf(rsq) + FEPS);

        float* hrow = g_H + ((size_t)(b0 + w) * SEQN + t) * HIDN;
#pragma unroll
        for (int i = 0; i < 8; ++i) {
            hh[i] = res[i] * rinv;
            cs[(lane + 32 * i) * CSS + w] = hh[i];   // next step's GEMM operand
            hrow[lane + 32 * i] = hh[i];             // history for out GEMM
        }

        if (t + 1 < SEQN) {
#pragma unroll
            for (int i = 0; i < 4; ++i)
                xr[i] = x[((size_t)(b0 + w) * SEQN + t + 1) * INPN + lane + 32 * i];
        }
        // cs writes are ordered before next phase A by S1 of the next iteration
    }

    if (hfin) {
#pragma unroll
        for (int i = 0; i < 8; ++i)
            hfin[(size_t)(b0 + w) * HIDN + lane + 32 * i] = hh[i];
    }
}

// out[row][c] = s_z * sum_j H[row][j]*Wout[j][c]; row = b*SEQN + t (same order as out)
#define OB_ROWS 64
#define HSTR    68
__global__ void __launch_bounds__(256, 2) nlnn_out(
    const float* __restrict__ Wout, const float* __restrict__ s_z_p,
    float* __restrict__ outp)
{
    extern __shared__ float sh[];                     // [256][HSTR] transposed H tile
    const int tid = threadIdx.x;
    const size_t row0 = (size_t)blockIdx.x * OB_ROWS;

#pragma unroll 8
    for (int i = 0; i < OB_ROWS; ++i)
        sh[tid * HSTR + i] = g_H[(row0 + i) * HIDN + tid];
    __syncthreads();

    const int c = tid & 63, rb = (tid >> 6) * 16;     // 4 groups x 16 rows
    const float sz = s_z_p[0];

    u64t acc[8];
#pragma unroll
    for (int p = 0; p < 8; ++p) acc[p] = 0ull;

#pragma unroll 4
    for (int j = 0; j < HIDN; ++j) {
        u64t b = dup2(Wout[j * OUTN + c]);
        const float* hp = sh + j * HSTR + rb;
        ulonglong2 hA = *(const ulonglong2*)(hp);
        ulonglong2 hB = *(const ulonglong2*)(hp + 4);
        ulonglong2 hC = *(const ulonglong2*)(hp + 8);
        ulonglong2 hD = *(const ulonglong2*)(hp + 12);
        ffma2(acc[0], hA.x, b); ffma2(acc[1], hA.y, b);
        ffma2(acc[2], hB.x, b); ffma2(acc[3], hB.y, b);
        ffma2(acc[4], hC.x, b); ffma2(acc[5], hC.y, b);
        ffma2(acc[6], hD.x, b); ffma2(acc[7], hD.y, b);
    }
#pragma unroll
    for (int p = 0; p < 8; ++p) {
        size_t r = row0 + rb + 2 * p;
        outp[r * OUTN + c]       = sz * lo2(acc[p]);
        outp[(r + 1) * OUTN + c] = sz * hi2(acc[p]);
    }
}

extern "C" void kernel_launch(void* const* d_in, const int* in_sizes, int n_in,
                              void* d_out, int out_size) {
    const float* x      = (const float*)d_in[0];
    const float* h_init = (const float*)d_in[1];
    const float* Win    = (const float*)d_in[2];
    const float* Wrec   = (const float*)d_in[3];
    const float* Wout   = (const float*)d_in[4];
    const float* li     = (const float*)d_in[5];
    const float* lr     = (const float*)d_in[6];
    const float* sz     = (const float*)d_in[7];
    const float* ar     = (const float*)d_in[8];

    float* outp = (float*)d_out;
    long long main_elems = (long long)BATCHN * SEQN * OUTN;
    float* hfin = nullptr;
    if ((long long)out_size >= main_elems + (long long)BATCHN * HIDN)
        hfin = outp + main_elems;

    int smem_main = (KTOT * CSS + 4 * ROWS * HIDN) * (int)sizeof(float);
    int smem_out  = (HIDN * HSTR) * (int)sizeof(float);
    cudaFuncSetAttribute(nlnn_main, cudaFuncAttributeMaxDynamicSharedMemorySize, smem_main);
    cudaFuncSetAttribute(nlnn_out,  cudaFuncAttributeMaxDynamicSharedMemorySize, smem_out);

    prep_kernel<<<KTOT, HIDN>>>(Win, Wrec, li, lr);
    nlnn_main<<<BATCHN / ROWS, NTHR, smem_main>>>(x, h_init, ar, hfin);
    nlnn_out<<<(BATCHN * SEQN) / OB_ROWS, 256, smem_out>>>(Wout, sz, outp);
}